// round 12
// baseline (speedup 1.0000x reference)
#include <cuda_runtime.h>
#include <cuda_fp16.h>
#include <cstdint>
#include <math.h>

#define HID 128
#define SDF_THRESH 5e-05f
#define ROWB 272              // padded row stride (bytes) for fp16[128] rows

// shared-memory byte offsets (per-CTA dynamic, all 16B aligned)
#define SW_HI  0              // W2' hi: 128 rows x 272B = 34816  (W2'[m][k] = W2[k][m])
#define SW_LO  34816          // W2' lo: 34816
#define W2IMG_BYTES 69632     // hi+lo image, copied verbatim from gmem
#define OFF_W1 69632          // fp32 [3][128] = 1536
#define OFF_B1 71168          // 512
#define OFF_B2 71680          // 512
#define OFF_W3 72192          // 512
#define OFF_RES 72704         // fp32 [256] = 1024
#define OFF_MAP 73728         // int  [256] slot->lane map = 1024
#define OFF_TAB 74752         // float2[4096] softplus table = 32768
#define SMEM_TOTAL 107520     // 105 KB -> 2 CTAs/SM (215 KB of 228 KB)

#define BLOCK 224             // 7 warps: grid 293 ~= 296 resident slots (load balance)
#define TAB_N 4096

// Pre-converted W2 image (hi/lo fp16, smem layout) written by prep kernel.
__device__ __align__(16) unsigned char g_w2img[W2IMG_BYTES];
// Softplus piecewise-linear table: (value, next-value-minus-value) on [-16,16].
__device__ __align__(16) float2 g_sptab[TAB_N];

// Table softplus: max interp err 1.9e-6; fmaxf(r,x) handles both tails
// (softplus(x) > x for all x; for x>16 true value is x within 1.1e-7).
__device__ __forceinline__ float softplus_tab(const float2* __restrict__ tab, float x) {
    float t = fmaf(x, 128.0f, 2048.0f);
    t = fminf(fmaxf(t, 0.0f), 4095.0f);
    int i = (int)t;
    float dx = t - (float)i;
    float2 e = tab[i];
    return fmaxf(fmaf(e.y, dx, e.x), x);
}

__device__ __forceinline__ void ldsm4(uint32_t* r, uint32_t a) {
    asm volatile("ldmatrix.sync.aligned.m8n8.x4.shared.b16 {%0,%1,%2,%3}, [%4];"
        : "=r"(r[0]), "=r"(r[1]), "=r"(r[2]), "=r"(r[3]) : "r"(a));
}
__device__ __forceinline__ void mma16816(float* c, const uint32_t* a, const uint32_t* b) {
    asm volatile("mma.sync.aligned.m16n8k16.row.col.f32.f16.f16.f32 "
        "{%0,%1,%2,%3}, {%4,%5,%6,%7}, {%8,%9}, {%0,%1,%2,%3};"
        : "+f"(c[0]), "+f"(c[1]), "+f"(c[2]), "+f"(c[3])
        : "r"(a[0]), "r"(a[1]), "r"(a[2]), "r"(a[3]), "r"(b[0]), "r"(b[1]));
}

__device__ __forceinline__ uint32_t pack_h2(float lo, float hi) {
    __half2 h = __halves2half2(__float2half_rn(lo), __float2half_rn(hi));
    return *reinterpret_cast<uint32_t*>(&h);
}

// layer-1 B fragments for one 8-point group: thread (q) computes
// h[k = 16kt + 2q, 2q+1, 2q+8, 2q+9] for its point, hi + lo fp16 split.
__device__ __forceinline__ void layer1_frags(
    float qx, float qy, float qz, int q,
    const float* __restrict__ sW1, const float* __restrict__ sb1,
    const float2* __restrict__ tab,
    uint32_t (&bhi)[8][2], uint32_t (&blo)[8][2])
{
#pragma unroll
    for (int kt = 0; kt < 8; kt++) {
        int k0 = kt * 16 + 2 * q;
        float2 w0a = *(const float2*)(sW1 + k0);
        float2 w0b = *(const float2*)(sW1 + k0 + 8);
        float2 w1a = *(const float2*)(sW1 + 128 + k0);
        float2 w1b = *(const float2*)(sW1 + 128 + k0 + 8);
        float2 w2a = *(const float2*)(sW1 + 256 + k0);
        float2 w2b = *(const float2*)(sW1 + 256 + k0 + 8);
        float2 b1a = *(const float2*)(sb1 + k0);
        float2 b1b = *(const float2*)(sb1 + k0 + 8);
        float h00 = fminf(softplus_tab(tab, fmaf(qx, w0a.x, fmaf(qy, w1a.x, fmaf(qz, w2a.x, b1a.x)))), 60000.0f);
        float h01 = fminf(softplus_tab(tab, fmaf(qx, w0a.y, fmaf(qy, w1a.y, fmaf(qz, w2a.y, b1a.y)))), 60000.0f);
        float h08 = fminf(softplus_tab(tab, fmaf(qx, w0b.x, fmaf(qy, w1b.x, fmaf(qz, w2b.x, b1b.x)))), 60000.0f);
        float h09 = fminf(softplus_tab(tab, fmaf(qx, w0b.y, fmaf(qy, w1b.y, fmaf(qz, w2b.y, b1b.y)))), 60000.0f);
        bhi[kt][0] = pack_h2(h00, h01);
        bhi[kt][1] = pack_h2(h08, h09);
        __half t0 = __float2half_rn(h00), t1 = __float2half_rn(h01);
        __half t8 = __float2half_rn(h08), t9 = __float2half_rn(h09);
        blo[kt][0] = pack_h2(h00 - __half2float(t0), h01 - __half2float(t1));
        blo[kt][1] = pack_h2(h08 - __half2float(t8), h09 - __half2float(t9));
    }
}

// ---------------------------------------------------------------------------
// Warp-collective SDF eval with lane COMPACTION: only ceil(nact/8) groups of
// 8 points are evaluated; active lanes' points are packed into consecutive
// slots via a slot->lane map in smem. Arithmetic per point is unchanged.
// A = W2' fp16 hi/lo via ldmatrix; B = activations built in registers.
// Paired path shares every A-fragment load between two groups.
// Softplus via smem table (LDS pipe) instead of MUFU.
// ---------------------------------------------------------------------------
__device__ __noinline__ float sdf_eval_warp(float px, float py, float pz,
                                            bool need, float b3)
{
    extern __shared__ char dsm[];
    const int tid  = threadIdx.x;
    const int lane = tid & 31;
    const int q    = lane & 3;
    const int g    = lane >> 2;
    const int wbase = tid & ~31;
    const uint32_t smem0 = (uint32_t)__cvta_generic_to_shared(dsm);
    const float* sW1 = (const float*)(dsm + OFF_W1);
    const float* sb1 = (const float*)(dsm + OFF_B1);
    const float* sb2 = (const float*)(dsm + OFF_B2);
    const float* sW3 = (const float*)(dsm + OFF_W3);
    const float2* tab = (const float2*)(dsm + OFF_TAB);
    float* s_res = (float*)(dsm + OFF_RES);
    int*   s_map = (int*)(dsm + OFF_MAP);

    const uint32_t full = 0xFFFFFFFFu;
    const uint32_t bal = __ballot_sync(full, need);
    const int nact = __popc(bal);
    const int myslot = __popc(bal & ((1u << lane) - 1u));
    if (need) s_map[wbase + myslot] = lane;
    __syncwarp();    // map visible; also prior eval's s_res reads complete

    const int ngroups = (nact + 7) >> 3;
    const uint32_t lanebase =
        (uint32_t)((((lane >> 3) & 1) * 8 + (lane & 7)) * ROWB + (lane >> 4) * 16);

#pragma unroll 1
    for (int gb = 0; gb < ngroups; gb += 2) {
        const bool paired = (gb + 1) < ngroups;
        const int s0 = 8 * gb + g;
        const int src0 = (s0 < nact) ? s_map[wbase + s0] : 0;
        float q0x = __shfl_sync(full, px, src0);
        float q0y = __shfl_sync(full, py, src0);
        float q0z = __shfl_sync(full, pz, src0);

        if (paired) {
            const int s1 = s0 + 8;
            const int src1 = (s1 < nact) ? s_map[wbase + s1] : 0;
            float q1x = __shfl_sync(full, px, src1);
            float q1y = __shfl_sync(full, py, src1);
            float q1z = __shfl_sync(full, pz, src1);
            uint32_t h0[8][2], l0[8][2], h1[8][2], l1[8][2];
            layer1_frags(q0x, q0y, q0z, q, sW1, sb1, tab, h0, l0);
            layer1_frags(q1x, q1y, q1z, q, sW1, sb1, tab, h1, l1);

            float P0 = 0.f, P1 = 0.f, P2 = 0.f, P3 = 0.f;
#pragma unroll 2
            for (int mt = 0; mt < 8; mt++) {
                int o0 = mt * 16 + g, o1 = o0 + 8;
                float b2a = sb2[o0], b2b = sb2[o1];
                float c0[4] = {b2a, b2a, b2b, b2b};
                float c1[4] = {b2a, b2a, b2b, b2b};
                uint32_t abase = smem0 + (uint32_t)(mt * 16 * ROWB) + lanebase;
#pragma unroll
                for (int kt = 0; kt < 8; kt++) {
                    uint32_t ah[4], al[4];
                    ldsm4(ah, abase + SW_HI + kt * 32);
                    ldsm4(al, abase + SW_LO + kt * 32);
                    mma16816(c0, ah, h0[kt]);
                    mma16816(c0, ah, l0[kt]);
                    mma16816(c0, al, h0[kt]);
                    mma16816(c1, ah, h1[kt]);
                    mma16816(c1, ah, l1[kt]);
                    mma16816(c1, al, h1[kt]);
                }
                float w3a = sW3[o0], w3b = sW3[o1];
                P0 = fmaf(softplus_tab(tab, c0[0]), w3a,
                     fmaf(softplus_tab(tab, c0[2]), w3b, P0));
                P1 = fmaf(softplus_tab(tab, c0[1]), w3a,
                     fmaf(softplus_tab(tab, c0[3]), w3b, P1));
                P2 = fmaf(softplus_tab(tab, c1[0]), w3a,
                     fmaf(softplus_tab(tab, c1[2]), w3b, P2));
                P3 = fmaf(softplus_tab(tab, c1[1]), w3a,
                     fmaf(softplus_tab(tab, c1[3]), w3b, P3));
            }
            P0 += __shfl_xor_sync(full, P0, 4);
            P0 += __shfl_xor_sync(full, P0, 8);
            P0 += __shfl_xor_sync(full, P0, 16);
            P1 += __shfl_xor_sync(full, P1, 4);
            P1 += __shfl_xor_sync(full, P1, 8);
            P1 += __shfl_xor_sync(full, P1, 16);
            P2 += __shfl_xor_sync(full, P2, 4);
            P2 += __shfl_xor_sync(full, P2, 8);
            P2 += __shfl_xor_sync(full, P2, 16);
            P3 += __shfl_xor_sync(full, P3, 4);
            P3 += __shfl_xor_sync(full, P3, 8);
            P3 += __shfl_xor_sync(full, P3, 16);
            if (g == 0) {
                s_res[wbase + 8 * gb + 2 * q + 0] = P0;
                s_res[wbase + 8 * gb + 2 * q + 1] = P1;
                s_res[wbase + 8 * (gb + 1) + 2 * q + 0] = P2;
                s_res[wbase + 8 * (gb + 1) + 2 * q + 1] = P3;
            }
        } else {
            uint32_t bh[8][2], bl[8][2];
            layer1_frags(q0x, q0y, q0z, q, sW1, sb1, tab, bh, bl);

            float P0 = 0.f, P1 = 0.f;
#pragma unroll 2
            for (int mt = 0; mt < 8; mt++) {
                int o0 = mt * 16 + g, o1 = o0 + 8;
                float b2a = sb2[o0], b2b = sb2[o1];
                float c[4] = {b2a, b2a, b2b, b2b};
                uint32_t abase = smem0 + (uint32_t)(mt * 16 * ROWB) + lanebase;
#pragma unroll
                for (int kt = 0; kt < 8; kt++) {
                    uint32_t ah[4], al[4];
                    ldsm4(ah, abase + SW_HI + kt * 32);
                    ldsm4(al, abase + SW_LO + kt * 32);
                    mma16816(c, ah, bh[kt]);
                    mma16816(c, ah, bl[kt]);
                    mma16816(c, al, bh[kt]);
                }
                float w3a = sW3[o0], w3b = sW3[o1];
                P0 = fmaf(softplus_tab(tab, c[0]), w3a,
                     fmaf(softplus_tab(tab, c[2]), w3b, P0));
                P1 = fmaf(softplus_tab(tab, c[1]), w3a,
                     fmaf(softplus_tab(tab, c[3]), w3b, P1));
            }
            P0 += __shfl_xor_sync(full, P0, 4);
            P0 += __shfl_xor_sync(full, P0, 8);
            P0 += __shfl_xor_sync(full, P0, 16);
            P1 += __shfl_xor_sync(full, P1, 4);
            P1 += __shfl_xor_sync(full, P1, 8);
            P1 += __shfl_xor_sync(full, P1, 16);
            if (g == 0) {
                s_res[wbase + 8 * gb + 2 * q + 0] = P0;
                s_res[wbase + 8 * gb + 2 * q + 1] = P1;
            }
        }
    }
    __syncwarp();
    return b3 + s_res[wbase + myslot];   // valid for 'need' lanes; ignored otherwise
}

// ---------------------------------------------------------------------------
// Prep kernel: convert W2 -> hi/lo fp16 smem image + build softplus table.
// ---------------------------------------------------------------------------
__global__ void prep_kernel(const float* __restrict__ gW2)
{
    int idx = blockIdx.x * blockDim.x + threadIdx.x;
    if (idx < HID * HID) {
        int m = idx & 127, k = idx >> 7;
        float w = gW2[idx];
        __half h = __float2half_rn(w);
        __half l = __float2half_rn(w - __half2float(h));
        *(__half*)(g_w2img + SW_HI + m * ROWB + k * 2) = h;
        *(__half*)(g_w2img + SW_LO + m * ROWB + k * 2) = l;
    }
    if (idx < TAB_N) {
        float x0 = -16.0f + (float)idx * (1.0f / 128.0f);
        float x1 = x0 + (1.0f / 128.0f);
        float v0 = fmaxf(x0, 0.0f) + log1pf(expf(-fabsf(x0)));
        float v1 = fmaxf(x1, 0.0f) + log1pf(expf(-fabsf(x1)));
        g_sptab[idx] = make_float2(v0, v1 - v0);
    }
}

// ---------------------------------------------------------------------------
__global__ void __launch_bounds__(BLOCK, 2)
sphere_trace_kernel(const float* __restrict__ rays_d,
                    const float* __restrict__ rays_o,
                    const float* __restrict__ gW1,
                    const float* __restrict__ gb1,
                    const float* __restrict__ gb2,
                    const float* __restrict__ gW3,
                    const float* __restrict__ gb3,
                    float* __restrict__ out,
                    int n)
{
    extern __shared__ char dsm[];
    const int tid = threadIdx.x;

    // stage pre-converted W2 image + softplus table with vector copies
    {
        const uint4* src = (const uint4*)g_w2img;
        uint4* dst = (uint4*)dsm;
        for (int i = tid; i < W2IMG_BYTES / 16; i += blockDim.x)
            dst[i] = src[i];
        const uint4* tsrc = (const uint4*)g_sptab;
        uint4* tdst = (uint4*)(dsm + OFF_TAB);
        for (int i = tid; i < (TAB_N * 8) / 16; i += blockDim.x)
            tdst[i] = tsrc[i];
    }
    {
        float* sW1 = (float*)(dsm + OFF_W1);
        float* sb1 = (float*)(dsm + OFF_B1);
        float* sb2 = (float*)(dsm + OFF_B2);
        float* sW3 = (float*)(dsm + OFF_W3);
        for (int i = tid; i < 3 * HID; i += blockDim.x) sW1[i] = gW1[i];
        for (int i = tid; i < HID; i += blockDim.x) {
            sb1[i] = gb1[i];
            sb2[i] = gb2[i];
            sW3[i] = gW3[i];
        }
    }
    float b3 = gb3[0];
    __syncthreads();

    const int total = 2 * n;
    int t = blockIdx.x * blockDim.x + tid;
    const bool valid = (t < total);
    int tc  = valid ? t : (total - 1);
    int ray = tc >> 1;
    int ch  = tc & 1;
    float sgn = ch ? -1.0f : 1.0f;

    float dx = rays_d[ray * 3 + 0];
    float dy = rays_d[ray * 3 + 1];
    float dz = rays_d[ray * 3 + 2];
    float ox = rays_o[ray * 3 + 0];
    float oy = rays_o[ray * 3 + 1];
    float oz = rays_o[ray * 3 + 2];

    const uint32_t full = 0xFFFFFFFFu;

    // Initial eval at z=0: both channels of a ray share the SAME origin point,
    // so only even (ch==0) lanes evaluate; odd lanes take the partner's value.
    float z = 0.0f;
    float s0 = sdf_eval_warp(ox, oy, oz, valid && (ch == 0), b3);
    float s0p = __shfl_xor_sync(full, s0, 1);
    float next_sdf = (ch == 0) ? s0 : s0p;
    next_sdf = valid ? next_sdf : 0.0f;     // kill tail lanes immediately
    bool mask = valid;

#pragma unroll 1
    for (int it = 0; it < 6; it++) {
        float sdf_vals = mask ? next_sdf : 0.0f;
        if (sdf_vals <= SDF_THRESH) sdf_vals = 0.0f;
        mask = mask && (sdf_vals > SDF_THRESH);
        z = fmaf(sgn, sdf_vals, z);

        if (__any_sync(full, mask)) {
            float s = sdf_eval_warp(fmaf(z, dx, ox), fmaf(z, dy, oy),
                                    fmaf(z, dz, oz), mask, b3);
            next_sdf = mask ? s : 0.0f;
        } else {
            next_sdf = 0.0f;
        }

        bool fmask = next_sdf < 0.0f;
#pragma unroll 1
        for (int i = 0; i < 3; i++) {
            float step = 0.5f / (float)(1 << i);   // 0.5, 0.25, 0.125 exact
            if (__any_sync(full, fmask)) {
                float zc = fmask ? (z - step * sgn * sdf_vals) : z;
                float s2 = sdf_eval_warp(fmaf(zc, dx, ox), fmaf(zc, dy, oy),
                                         fmaf(zc, dz, oz), fmask, b3);
                z = zc;
                if (fmask) next_sdf = s2;
            }
            fmask = next_sdf < 0.0f;
        }

        // mask &= (z_ch0 < z_ch1): channels are adjacent lanes
        float zo = __shfl_xor_sync(full, z, 1);
        bool cond = (ch == 0) ? (z < zo) : (zo < z);
        mask = mask && cond;
    }

    {   // final top-of-loop mask update
        float sdf_vals = mask ? next_sdf : 0.0f;
        if (sdf_vals <= SDF_THRESH) sdf_vals = 0.0f;
        mask = mask && (sdf_vals > SDF_THRESH);
    }

    if (valid) {
        float px = fmaf(z, dx, ox);
        float py = fmaf(z, dy, oy);
        float pz = fmaf(z, dz, oz);
        long basei = (long)ch * n + ray;
        // output layout: points (2,n,3) | z_vals (2,n) | mask (2,n)
        out[basei * 3 + 0] = px;
        out[basei * 3 + 1] = py;
        out[basei * 3 + 2] = pz;
        out[(long)6 * n + basei] = z;
        out[(long)8 * n + basei] = mask ? 1.0f : 0.0f;
    }
}

extern "C" void kernel_launch(void* const* d_in, const int* in_sizes, int n_in,
                              void* d_out, int out_size)
{
    const float* rays_d = (const float*)d_in[0];
    const float* rays_o = (const float*)d_in[1];
    const float* W1     = (const float*)d_in[2];
    const float* b1     = (const float*)d_in[3];
    const float* W2     = (const float*)d_in[4];
    const float* b2     = (const float*)d_in[5];
    const float* W3     = (const float*)d_in[6];
    const float* b3     = (const float*)d_in[7];

    int n = in_sizes[0] / 3;        // N_RAYS
    int total = 2 * n;
    int block = BLOCK;
    int grid = (total + block - 1) / block;

    // 1) convert W2 + build softplus table once
    prep_kernel<<<(HID * HID + 255) / 256, 256>>>(W2);

    // 2) main trace (stages image + table with uint4 copies)
    cudaFuncSetAttribute(sphere_trace_kernel,
                         cudaFuncAttributeMaxDynamicSharedMemorySize,
                         SMEM_TOTAL);
    sphere_trace_kernel<<<grid, block, SMEM_TOTAL>>>(
        rays_d, rays_o, W1, b1, b2, W3, b3, (float*)d_out, n);
}

// round 13
// speedup vs baseline: 1.1476x; 1.1476x over previous
#include <cuda_runtime.h>
#include <cuda_fp16.h>
#include <cstdint>
#include <math.h>

#define HID 128
#define SDF_THRESH 5e-05f
#define ROWB 272              // padded row stride (bytes) for fp16[128] rows

// shared-memory byte offsets (per-CTA dynamic, all 16B aligned)
#define SW_HI  0              // W2' hi: 128 rows x 272B = 34816  (W2'[m][k] = W2[k][m])
#define SW_LO  34816          // W2' lo: 34816
#define W2IMG_BYTES 69632     // hi+lo image, copied verbatim from gmem
#define OFF_PK 69632          // float4[128]: {W1row0, W1row1, W1row2, b1} per k = 2048
#define OFF_B2 71680          // 512
#define OFF_W3 72192          // 512
#define OFF_RES 72704         // fp32 [256] = 1024
#define OFF_MAP 73728         // int  [256] slot->lane map = 1024
#define SMEM_TOTAL 74752      // 73 KB -> 2 CTAs/SM

#define BLOCK 224             // 7 warps: grid 293 ~= 296 resident slots (load balance)

// Pre-converted W2 image (hi/lo fp16, smem layout) written by prep kernel.
__device__ __align__(16) unsigned char g_w2img[W2IMG_BYTES];

// softplus: max(x,0) + log(1 + exp(-|x|))   (proven R11 form)
__device__ __forceinline__ float softplusf(float x) {
    float u = __expf(-fabsf(x));
    return fmaxf(x, 0.0f) + __logf(1.0f + u);
}

__device__ __forceinline__ void ldsm4(uint32_t* r, uint32_t a) {
    asm volatile("ldmatrix.sync.aligned.m8n8.x4.shared.b16 {%0,%1,%2,%3}, [%4];"
        : "=r"(r[0]), "=r"(r[1]), "=r"(r[2]), "=r"(r[3]) : "r"(a));
}
__device__ __forceinline__ void mma16816(float* c, const uint32_t* a, const uint32_t* b) {
    asm volatile("mma.sync.aligned.m16n8k16.row.col.f32.f16.f16.f32 "
        "{%0,%1,%2,%3}, {%4,%5,%6,%7}, {%8,%9}, {%0,%1,%2,%3};"
        : "+f"(c[0]), "+f"(c[1]), "+f"(c[2]), "+f"(c[3])
        : "r"(a[0]), "r"(a[1]), "r"(a[2]), "r"(a[3]), "r"(b[0]), "r"(b[1]));
}

__device__ __forceinline__ uint32_t pack_h2(float lo, float hi) {
    __half2 h = __halves2half2(__float2half_rn(lo), __float2half_rn(hi));
    return *reinterpret_cast<uint32_t*>(&h);
}

// layer-1 B fragments for one 8-point group: thread (q) computes
// h[k = 16kt + 2q, 2q+1, 2q+8, 2q+9] for its point, hi + lo fp16 split.
// PK[k] = {w1r0[k], w1r1[k], w1r2[k], b1[k]} -> one LDS.128 per h value.
__device__ __forceinline__ void layer1_frags(
    float qx, float qy, float qz, int q,
    const float4* __restrict__ PK,
    uint32_t (&bhi)[8][2], uint32_t (&blo)[8][2])
{
#pragma unroll
    for (int kt = 0; kt < 8; kt++) {
        int k0 = kt * 16 + 2 * q;
        float4 A = PK[k0];
        float4 B = PK[k0 + 1];
        float4 C = PK[k0 + 8];
        float4 D = PK[k0 + 9];
        float h00 = fminf(softplusf(fmaf(qx, A.x, fmaf(qy, A.y, fmaf(qz, A.z, A.w)))), 60000.0f);
        float h01 = fminf(softplusf(fmaf(qx, B.x, fmaf(qy, B.y, fmaf(qz, B.z, B.w)))), 60000.0f);
        float h08 = fminf(softplusf(fmaf(qx, C.x, fmaf(qy, C.y, fmaf(qz, C.z, C.w)))), 60000.0f);
        float h09 = fminf(softplusf(fmaf(qx, D.x, fmaf(qy, D.y, fmaf(qz, D.z, D.w)))), 60000.0f);
        bhi[kt][0] = pack_h2(h00, h01);
        bhi[kt][1] = pack_h2(h08, h09);
        __half t0 = __float2half_rn(h00), t1 = __float2half_rn(h01);
        __half t8 = __float2half_rn(h08), t9 = __float2half_rn(h09);
        blo[kt][0] = pack_h2(h00 - __half2float(t0), h01 - __half2float(t1));
        blo[kt][1] = pack_h2(h08 - __half2float(t8), h09 - __half2float(t9));
    }
}

// ---------------------------------------------------------------------------
// Warp-collective SDF eval with lane COMPACTION: only ceil(nact/8) groups of
// 8 points are evaluated; active lanes' points are packed into consecutive
// slots via a slot->lane map in smem. Arithmetic per point is unchanged.
// A = W2' fp16 hi/lo via ldmatrix; B = activations built in registers.
// Paired path shares every A-fragment load between two groups.
// mt loops unrolled x2 so next tile's ldsm overlaps current tile's HMMAs.
// ---------------------------------------------------------------------------
__device__ __noinline__ float sdf_eval_warp(float px, float py, float pz,
                                            bool need, float b3)
{
    extern __shared__ char dsm[];
    const int tid  = threadIdx.x;
    const int lane = tid & 31;
    const int q    = lane & 3;
    const int g    = lane >> 2;
    const int wbase = tid & ~31;
    const uint32_t smem0 = (uint32_t)__cvta_generic_to_shared(dsm);
    const float4* PK = (const float4*)(dsm + OFF_PK);
    const float* sb2 = (const float*)(dsm + OFF_B2);
    const float* sW3 = (const float*)(dsm + OFF_W3);
    float* s_res = (float*)(dsm + OFF_RES);
    int*   s_map = (int*)(dsm + OFF_MAP);

    const uint32_t full = 0xFFFFFFFFu;
    const uint32_t bal = __ballot_sync(full, need);
    const int nact = __popc(bal);
    const int myslot = __popc(bal & ((1u << lane) - 1u));
    if (need) s_map[wbase + myslot] = lane;
    __syncwarp();    // map visible; also prior eval's s_res reads complete

    const int ngroups = (nact + 7) >> 3;
    const uint32_t lanebase =
        (uint32_t)((((lane >> 3) & 1) * 8 + (lane & 7)) * ROWB + (lane >> 4) * 16);

#pragma unroll 1
    for (int gb = 0; gb < ngroups; gb += 2) {
        const bool paired = (gb + 1) < ngroups;
        const int s0 = 8 * gb + g;
        const int src0 = (s0 < nact) ? s_map[wbase + s0] : 0;
        float q0x = __shfl_sync(full, px, src0);
        float q0y = __shfl_sync(full, py, src0);
        float q0z = __shfl_sync(full, pz, src0);

        if (paired) {
            const int s1 = s0 + 8;
            const int src1 = (s1 < nact) ? s_map[wbase + s1] : 0;
            float q1x = __shfl_sync(full, px, src1);
            float q1y = __shfl_sync(full, py, src1);
            float q1z = __shfl_sync(full, pz, src1);
            uint32_t h0[8][2], l0[8][2], h1[8][2], l1[8][2];
            layer1_frags(q0x, q0y, q0z, q, PK, h0, l0);
            layer1_frags(q1x, q1y, q1z, q, PK, h1, l1);

            float P0 = 0.f, P1 = 0.f, P2 = 0.f, P3 = 0.f;
#pragma unroll 2
            for (int mt = 0; mt < 8; mt++) {
                int o0 = mt * 16 + g, o1 = o0 + 8;
                float b2a = sb2[o0], b2b = sb2[o1];
                float c0[4] = {b2a, b2a, b2b, b2b};
                float c1[4] = {b2a, b2a, b2b, b2b};
                uint32_t abase = smem0 + (uint32_t)(mt * 16 * ROWB) + lanebase;
#pragma unroll
                for (int kt = 0; kt < 8; kt++) {
                    uint32_t ah[4], al[4];
                    ldsm4(ah, abase + SW_HI + kt * 32);
                    ldsm4(al, abase + SW_LO + kt * 32);
                    mma16816(c0, ah, h0[kt]);
                    mma16816(c0, ah, l0[kt]);
                    mma16816(c0, al, h0[kt]);
                    mma16816(c1, ah, h1[kt]);
                    mma16816(c1, ah, l1[kt]);
                    mma16816(c1, al, h1[kt]);
                }
                float w3a = sW3[o0], w3b = sW3[o1];
                P0 = fmaf(softplusf(c0[0]), w3a, fmaf(softplusf(c0[2]), w3b, P0));
                P1 = fmaf(softplusf(c0[1]), w3a, fmaf(softplusf(c0[3]), w3b, P1));
                P2 = fmaf(softplusf(c1[0]), w3a, fmaf(softplusf(c1[2]), w3b, P2));
                P3 = fmaf(softplusf(c1[1]), w3a, fmaf(softplusf(c1[3]), w3b, P3));
            }
            P0 += __shfl_xor_sync(full, P0, 4);
            P0 += __shfl_xor_sync(full, P0, 8);
            P0 += __shfl_xor_sync(full, P0, 16);
            P1 += __shfl_xor_sync(full, P1, 4);
            P1 += __shfl_xor_sync(full, P1, 8);
            P1 += __shfl_xor_sync(full, P1, 16);
            P2 += __shfl_xor_sync(full, P2, 4);
            P2 += __shfl_xor_sync(full, P2, 8);
            P2 += __shfl_xor_sync(full, P2, 16);
            P3 += __shfl_xor_sync(full, P3, 4);
            P3 += __shfl_xor_sync(full, P3, 8);
            P3 += __shfl_xor_sync(full, P3, 16);
            if (g == 0) {
                s_res[wbase + 8 * gb + 2 * q + 0] = P0;
                s_res[wbase + 8 * gb + 2 * q + 1] = P1;
                s_res[wbase + 8 * (gb + 1) + 2 * q + 0] = P2;
                s_res[wbase + 8 * (gb + 1) + 2 * q + 1] = P3;
            }
        } else {
            uint32_t bh[8][2], bl[8][2];
            layer1_frags(q0x, q0y, q0z, q, PK, bh, bl);

            float P0 = 0.f, P1 = 0.f;
#pragma unroll 2
            for (int mt = 0; mt < 8; mt++) {
                int o0 = mt * 16 + g, o1 = o0 + 8;
                float b2a = sb2[o0], b2b = sb2[o1];
                float c[4] = {b2a, b2a, b2b, b2b};
                uint32_t abase = smem0 + (uint32_t)(mt * 16 * ROWB) + lanebase;
#pragma unroll
                for (int kt = 0; kt < 8; kt++) {
                    uint32_t ah[4], al[4];
                    ldsm4(ah, abase + SW_HI + kt * 32);
                    ldsm4(al, abase + SW_LO + kt * 32);
                    mma16816(c, ah, bh[kt]);
                    mma16816(c, ah, bl[kt]);
                    mma16816(c, al, bh[kt]);
                }
                float w3a = sW3[o0], w3b = sW3[o1];
                P0 = fmaf(softplusf(c[0]), w3a, fmaf(softplusf(c[2]), w3b, P0));
                P1 = fmaf(softplusf(c[1]), w3a, fmaf(softplusf(c[3]), w3b, P1));
            }
            P0 += __shfl_xor_sync(full, P0, 4);
            P0 += __shfl_xor_sync(full, P0, 8);
            P0 += __shfl_xor_sync(full, P0, 16);
            P1 += __shfl_xor_sync(full, P1, 4);
            P1 += __shfl_xor_sync(full, P1, 8);
            P1 += __shfl_xor_sync(full, P1, 16);
            if (g == 0) {
                s_res[wbase + 8 * gb + 2 * q + 0] = P0;
                s_res[wbase + 8 * gb + 2 * q + 1] = P1;
            }
        }
    }
    __syncwarp();
    return b3 + s_res[wbase + myslot];   // valid for 'need' lanes; ignored otherwise
}

// ---------------------------------------------------------------------------
// Prep kernel: convert W2 -> hi/lo fp16 smem image once (instead of per-CTA).
// ---------------------------------------------------------------------------
__global__ void prep_kernel(const float* __restrict__ gW2)
{
    int idx = blockIdx.x * blockDim.x + threadIdx.x;
    if (idx < HID * HID) {
        int m = idx & 127, k = idx >> 7;
        float w = gW2[idx];
        __half h = __float2half_rn(w);
        __half l = __float2half_rn(w - __half2float(h));
        *(__half*)(g_w2img + SW_HI + m * ROWB + k * 2) = h;
        *(__half*)(g_w2img + SW_LO + m * ROWB + k * 2) = l;
    }
}

// ---------------------------------------------------------------------------
__global__ void __launch_bounds__(BLOCK, 2)
sphere_trace_kernel(const float* __restrict__ rays_d,
                    const float* __restrict__ rays_o,
                    const float* __restrict__ gW1,
                    const float* __restrict__ gb1,
                    const float* __restrict__ gb2,
                    const float* __restrict__ gW3,
                    const float* __restrict__ gb3,
                    float* __restrict__ out,
                    int n)
{
    extern __shared__ char dsm[];
    const int tid = threadIdx.x;

    // stage pre-converted W2 image with vector copies (coalesced, no converts)
    {
        const uint4* src = (const uint4*)g_w2img;
        uint4* dst = (uint4*)dsm;
        for (int i = tid; i < W2IMG_BYTES / 16; i += blockDim.x)
            dst[i] = src[i];
    }
    {
        float4* PK = (float4*)(dsm + OFF_PK);
        float* sb2 = (float*)(dsm + OFF_B2);
        float* sW3 = (float*)(dsm + OFF_W3);
        for (int k = tid; k < HID; k += blockDim.x) {
            PK[k] = make_float4(gW1[k], gW1[128 + k], gW1[256 + k], gb1[k]);
            sb2[k] = gb2[k];
            sW3[k] = gW3[k];
        }
    }
    float b3 = gb3[0];
    __syncthreads();

    const int total = 2 * n;
    int t = blockIdx.x * blockDim.x + tid;
    const bool valid = (t < total);
    int tc  = valid ? t : (total - 1);
    int ray = tc >> 1;
    int ch  = tc & 1;
    float sgn = ch ? -1.0f : 1.0f;

    float dx = rays_d[ray * 3 + 0];
    float dy = rays_d[ray * 3 + 1];
    float dz = rays_d[ray * 3 + 2];
    float ox = rays_o[ray * 3 + 0];
    float oy = rays_o[ray * 3 + 1];
    float oz = rays_o[ray * 3 + 2];

    const uint32_t full = 0xFFFFFFFFu;

    // Initial eval at z=0: both channels of a ray share the SAME origin point,
    // so only even (ch==0) lanes evaluate; odd lanes take the partner's value.
    float z = 0.0f;
    float s0 = sdf_eval_warp(ox, oy, oz, valid && (ch == 0), b3);
    float s0p = __shfl_xor_sync(full, s0, 1);
    float next_sdf = (ch == 0) ? s0 : s0p;
    next_sdf = valid ? next_sdf : 0.0f;     // kill tail lanes immediately
    bool mask = valid;

#pragma unroll 1
    for (int it = 0; it < 6; it++) {
        float sdf_vals = mask ? next_sdf : 0.0f;
        if (sdf_vals <= SDF_THRESH) sdf_vals = 0.0f;
        mask = mask && (sdf_vals > SDF_THRESH);
        z = fmaf(sgn, sdf_vals, z);

        if (__any_sync(full, mask)) {
            float s = sdf_eval_warp(fmaf(z, dx, ox), fmaf(z, dy, oy),
                                    fmaf(z, dz, oz), mask, b3);
            next_sdf = mask ? s : 0.0f;
        } else {
            next_sdf = 0.0f;
        }

        bool fmask = next_sdf < 0.0f;
#pragma unroll 1
        for (int i = 0; i < 3; i++) {
            float step = 0.5f / (float)(1 << i);   // 0.5, 0.25, 0.125 exact
            if (__any_sync(full, fmask)) {
                float zc = fmask ? (z - step * sgn * sdf_vals) : z;
                float s2 = sdf_eval_warp(fmaf(zc, dx, ox), fmaf(zc, dy, oy),
                                         fmaf(zc, dz, oz), fmask, b3);
                z = zc;
                if (fmask) next_sdf = s2;
            }
            fmask = next_sdf < 0.0f;
        }

        // mask &= (z_ch0 < z_ch1): channels are adjacent lanes
        float zo = __shfl_xor_sync(full, z, 1);
        bool cond = (ch == 0) ? (z < zo) : (zo < z);
        mask = mask && cond;
    }

    {   // final top-of-loop mask update
        float sdf_vals = mask ? next_sdf : 0.0f;
        if (sdf_vals <= SDF_THRESH) sdf_vals = 0.0f;
        mask = mask && (sdf_vals > SDF_THRESH);
    }

    if (valid) {
        float px = fmaf(z, dx, ox);
        float py = fmaf(z, dy, oy);
        float pz = fmaf(z, dz, oz);
        long basei = (long)ch * n + ray;
        // output layout: points (2,n,3) | z_vals (2,n) | mask (2,n)
        out[basei * 3 + 0] = px;
        out[basei * 3 + 1] = py;
        out[basei * 3 + 2] = pz;
        out[(long)6 * n + basei] = z;
        out[(long)8 * n + basei] = mask ? 1.0f : 0.0f;
    }
}

extern "C" void kernel_launch(void* const* d_in, const int* in_sizes, int n_in,
                              void* d_out, int out_size)
{
    const float* rays_d = (const float*)d_in[0];
    const float* rays_o = (const float*)d_in[1];
    const float* W1     = (const float*)d_in[2];
    const float* b1     = (const float*)d_in[3];
    const float* W2     = (const float*)d_in[4];
    const float* b2     = (const float*)d_in[5];
    const float* W3     = (const float*)d_in[6];
    const float* b3     = (const float*)d_in[7];

    int n = in_sizes[0] / 3;        // N_RAYS
    int total = 2 * n;
    int block = BLOCK;
    int grid = (total + block - 1) / block;

    // 1) convert W2 once into the gmem image
    prep_kernel<<<(HID * HID + 255) / 256, 256>>>(W2);

    // 2) main trace (stages the image with uint4 copies)
    cudaFuncSetAttribute(sphere_trace_kernel,
                         cudaFuncAttributeMaxDynamicSharedMemorySize,
                         SMEM_TOTAL);
    sphere_trace_kernel<<<grid, block, SMEM_TOTAL>>>(
        rays_d, rays_o, W1, b1, b2, W3, b3, (float*)d_out, n);
}